// round 1
// baseline (speedup 1.0000x reference)
#include <cuda_runtime.h>

// LSTM_36318243455658 — persistent per-batch-element fp32 LSTM using packed
// f32x2 FFMA (sm_103a FFMA2) for the recurrent matvec.
//
// Shapes: x[16384, 2048, 1] f32, w_ih[200,1], w_hh[200,50], b_ih[200],
//         b_hh[200], w_fc[1,50], b_fc[1]  -> out[16384,1] f32.
//
// 1 thread = 1 batch element. h kept in registers as 25 packed f32x2 pairs
// (pairs along k). w_hh in shared (broadcast reads). c / h_new in per-thread
// shared slices (dynamic j index without register-array spills).

#define HH    50
#define KP    25          // packed f32x2 pairs per hidden vector
#define G4    200         // 4*HH gate rows
#define TT    2048
#define NB    16384
#define TPB   128
#define WROW  52          // padded floats per w_hh row (16B-aligned rows)
#define CPAD  52          // padded per-thread c / h_new slice

// dynamic smem layout (floats):
//   sW  : G4*WROW                    (41600 B)
//   sIB : G4 float2 (w_ih, b_ih+b_hh) (1600 B)
//   sFC : 52                          (208 B)
//   sC  : TPB*CPAD                    (26624 B)
//   sHN : TPB*CPAD                    (26624 B)
#define SMEM_BYTES (G4*WROW*4 + G4*8 + 52*4 + TPB*CPAD*4*2)

__device__ __forceinline__ void ffma2(unsigned long long &d,
                                      unsigned long long a,
                                      unsigned long long b) {
    // packed fp32x2 fused multiply-add: d = a*b + d (both lanes)
    asm("fma.rn.f32x2 %0, %1, %2, %0;" : "+l"(d) : "l"(a), "l"(b));
}

__device__ __forceinline__ float hsum2(unsigned long long v) {
    union { unsigned long long u; float2 f; } cv; cv.u = v;
    return cv.f.x + cv.f.y;
}

// numerically safe fast tanh: exp of a non-positive argument only
__device__ __forceinline__ float tanh_fast(float x) {
    float ax = fabsf(x);
    float e  = __expf(-2.0f * ax);            // in (0, 1]
    float r  = __fdividef(1.0f - e, 1.0f + e);
    return copysignf(r, x);
}
__device__ __forceinline__ float sigmoid_fast(float x) {
    return fmaf(0.5f, tanh_fast(0.5f * x), 0.5f);
}

__global__ void __launch_bounds__(TPB, 1)
lstm_kernel(const float* __restrict__ x,
            const float* __restrict__ w_ih,
            const float* __restrict__ w_hh,
            const float* __restrict__ b_ih,
            const float* __restrict__ b_hh,
            const float* __restrict__ w_fc,
            const float* __restrict__ b_fc,
            float* __restrict__ out)
{
    extern __shared__ float smem[];
    float*  sW  = smem;                              // [G4][WROW]
    float2* sIB = (float2*)(sW + G4 * WROW);         // [G4]
    float*  sFC = (float*)(sIB + G4);                // [52]
    float*  sC  = sFC + 52;                          // [TPB][CPAD]
    float*  sHN = sC + TPB * CPAD;                   // [TPB][CPAD]

    const int tid = threadIdx.x;

    // cooperative weight staging
    for (int i = tid; i < G4 * HH; i += TPB) {
        int r = i / HH;
        int k = i - r * HH;
        sW[r * WROW + k] = w_hh[i];
    }
    for (int r = tid; r < G4; r += TPB) {
        sW[r * WROW + 50] = 0.0f;
        sW[r * WROW + 51] = 0.0f;
        sIB[r] = make_float2(w_ih[r], b_ih[r] + b_hh[r]);
    }
    if (tid < 52) sFC[tid] = (tid < HH) ? w_fc[tid] : 0.0f;
    __syncthreads();

    const int b = blockIdx.x * TPB + tid;
    const float* xrow = x + (long long)b * TT;

    unsigned long long h2[KP];
#pragma unroll
    for (int p = 0; p < KP; p++) h2[p] = 0ull;

    float* myC = sC  + tid * CPAD;
    float* myH = sHN + tid * CPAD;
    for (int j = 0; j < HH; j++) myC[j] = 0.0f;

    float xc = xrow[0];

    for (int t = 0; t < TT; t++) {
        // prefetch next x one step ahead (clamped at the end)
        int tn = t + 1;
        if (tn >= TT) tn = TT - 1;
        float xn = __ldg(xrow + tn);

#pragma unroll 1
        for (int j = 0; j < HH; j++) {
            const ulonglong2* pi = (const ulonglong2*)(sW + (j           ) * WROW);
            const ulonglong2* pf = (const ulonglong2*)(sW + (j +     HH ) * WROW);
            const ulonglong2* pg = (const ulonglong2*)(sW + (j + 2 * HH ) * WROW);
            const ulonglong2* po = (const ulonglong2*)(sW + (j + 3 * HH ) * WROW);

            unsigned long long ai = 0ull, af = 0ull, ag = 0ull, ao = 0ull;

#pragma unroll
            for (int p = 0; p < 12; p++) {
                ulonglong2 wi = pi[p];
                ulonglong2 wf = pf[p];
                ulonglong2 wg = pg[p];
                ulonglong2 wo = po[p];
                unsigned long long ha = h2[2 * p];
                unsigned long long hb = h2[2 * p + 1];
                ffma2(ai, wi.x, ha);  ffma2(af, wf.x, ha);
                ffma2(ag, wg.x, ha);  ffma2(ao, wo.x, ha);
                ffma2(ai, wi.y, hb);  ffma2(af, wf.y, hb);
                ffma2(ag, wg.y, hb);  ffma2(ao, wo.y, hb);
            }
            {   // tail pair (k = 48, 49)
                unsigned long long wi = ((const unsigned long long*)pi)[24];
                unsigned long long wf = ((const unsigned long long*)pf)[24];
                unsigned long long wg = ((const unsigned long long*)pg)[24];
                unsigned long long wo = ((const unsigned long long*)po)[24];
                unsigned long long ht = h2[24];
                ffma2(ai, wi, ht);  ffma2(af, wf, ht);
                ffma2(ag, wg, ht);  ffma2(ao, wo, ht);
            }

            float2 ib;
            ib = sIB[j];            float gi = hsum2(ai) + fmaf(xc, ib.x, ib.y);
            ib = sIB[j +     HH];   float gf = hsum2(af) + fmaf(xc, ib.x, ib.y);
            ib = sIB[j + 2 * HH];   float gg = hsum2(ag) + fmaf(xc, ib.x, ib.y);
            ib = sIB[j + 3 * HH];   float go = hsum2(ao) + fmaf(xc, ib.x, ib.y);

            float I = sigmoid_fast(gi);
            float F = sigmoid_fast(gf);
            float G = tanh_fast(gg);
            float O = sigmoid_fast(go);

            float cn = fmaf(F, myC[j], I * G);
            myC[j] = cn;
            myH[j] = O * tanh_fast(cn);
        }

        // repack new h into registers (aligned 8B loads from own slice)
        const unsigned long long* hn = (const unsigned long long*)myH;
#pragma unroll
        for (int p = 0; p < KP; p++) h2[p] = hn[p];

        xc = xn;
    }

    // fc head on last hidden state
    float acc = b_fc[0];
#pragma unroll
    for (int p = 0; p < KP; p++) {
        union { unsigned long long u; float2 f; } cv; cv.u = h2[p];
        acc = fmaf(cv.f.x, sFC[2 * p],     acc);
        acc = fmaf(cv.f.y, sFC[2 * p + 1], acc);
    }
    out[b] = acc;
}

extern "C" void kernel_launch(void* const* d_in, const int* in_sizes, int n_in,
                              void* d_out, int out_size) {
    const float* x    = (const float*)d_in[0];
    const float* w_ih = (const float*)d_in[1];
    const float* w_hh = (const float*)d_in[2];
    const float* b_ih = (const float*)d_in[3];
    const float* b_hh = (const float*)d_in[4];
    const float* w_fc = (const float*)d_in[5];
    const float* b_fc = (const float*)d_in[6];
    float* out = (float*)d_out;

    cudaFuncSetAttribute(lstm_kernel,
                         cudaFuncAttributeMaxDynamicSharedMemorySize,
                         SMEM_BYTES);
    lstm_kernel<<<NB / TPB, TPB, SMEM_BYTES>>>(x, w_ih, w_hh, b_ih, b_hh,
                                               w_fc, b_fc, out);
}

// round 4
// speedup vs baseline: 2.9731x; 2.9731x over previous
#include <cuda_runtime.h>
#include <cuda_fp16.h>
#include <cstdint>

// LSTM_36318243455658 — warp-level HMMA (mma.sync m16n8k16 f16/f32) batched
// LSTM. CTA = 128 batch rows, 8 warps x 16 rows. Per step per warp:
// D[16,200] = A[16,64] x B[64,200], A = [h | x_t | 1 | pad] (f16, smem),
// B = [w_hh | w_ih | b_ih+b_hh | pad] gate-interleaved (n = 4j+gate).
// Epilogue: shfl-exchange -> full gates per lane -> fp32 activations ->
// c update (registers) -> h write-back (f16, own rows). No CTA sync in loop.

#define TT    2048
#define NB    16384
#define ROWS  128
#define NCTA  (NB / ROWS)
#define TPB   256
#define SA    72      // halves per A row (144 B stride: bank = 4g+tg, clean)
#define SB    72      // halves per B row

__device__ __forceinline__ uint32_t lds32(const half* p) {
    return *reinterpret_cast<const uint32_t*>(p);
}

__device__ __forceinline__ void mma16816(float& d0, float& d1, float& d2, float& d3,
                                         uint32_t a0, uint32_t a1, uint32_t a2, uint32_t a3,
                                         uint32_t b0, uint32_t b1) {
    asm volatile(
        "mma.sync.aligned.m16n8k16.row.col.f32.f16.f16.f32 "
        "{%0,%1,%2,%3}, {%4,%5,%6,%7}, {%8,%9}, {%0,%1,%2,%3};"
        : "+f"(d0), "+f"(d1), "+f"(d2), "+f"(d3)
        : "r"(a0), "r"(a1), "r"(a2), "r"(a3), "r"(b0), "r"(b1));
}

// numerically safe fast activations (fp32, MUFU ex2/rcp based)
__device__ __forceinline__ float sigf(float x) {
    return __fdividef(1.0f, 1.0f + __expf(-x));
}
__device__ __forceinline__ float tanhf_s(float x) {
    float ax = fabsf(x);
    float e  = __expf(-2.0f * ax);
    float r  = __fdividef(1.0f - e, 1.0f + e);
    return copysignf(r, x);
}

__global__ void __launch_bounds__(TPB, 1)
lstm_mma_kernel(const float* __restrict__ x,
                const float* __restrict__ w_ih,
                const float* __restrict__ w_hh,
                const float* __restrict__ b_ih,
                const float* __restrict__ b_hh,
                const float* __restrict__ w_fc,
                const float* __restrict__ b_fc,
                float* __restrict__ out)
{
    __shared__ __align__(16) half As[ROWS * SA];   // 18432 B
    __shared__ __align__(16) half Bs[200 * SB];    // 28800 B
    __shared__ float FC[52];

    const int tid  = threadIdx.x;
    const int wid  = tid >> 5;
    const int lane = tid & 31;
    const int g    = lane >> 2;          // 0..7
    const int tg   = lane & 3;           // 0..3
    const int wb   = wid * 16;           // warp's row base in tile
    const long long ctabase = (long long)blockIdx.x * ROWS;

    // ---- staging ----
    // zero A (h0 = 0, pads = 0)
    for (int i = tid; i < ROWS * SA / 2; i += TPB)
        reinterpret_cast<uint32_t*>(As)[i] = 0u;
    // B: n = 4j + gate, k-major, k<50: w_hh row; 50: w_ih; 51: bias sum; pad 0
    for (int i = tid; i < 200 * SB; i += TPB) {
        int n = i / SB, k = i - n * SB;
        int j = n >> 2, gt = n & 3;
        int orig = gt * 50 + j;          // PyTorch gate order rows: i,f,g,o
        float v = 0.0f;
        if (k < 50)       v = w_hh[orig * 50 + k];
        else if (k == 50) v = w_ih[orig];
        else if (k == 51) v = b_ih[orig] + b_hh[orig];
        Bs[i] = __float2half_rn(v);
    }
    if (tid < 50) FC[tid] = w_fc[tid];
    __syncthreads();
    // x_0 and the constant-1 column
    if (tid < ROWS) {
        float x0 = __ldg(x + (ctabase + tid) * TT);
        As[tid * SA + 50] = __float2half_rn(x0);
        As[tid * SA + 51] = __float2half_rn(1.0f);
    }
    __syncthreads();

    const int  rowloc = g + (tg & 1) * 8;          // this lane's result row
    half*      hdst   = As + (wb + rowloc) * SA;   // write base for h
    const bool ev     = (tg & 1) == 0;
    const int  jofs   = (tg >> 1);                 // 0: even j, 1: odd j
    const float* xlane = x + (ctabase + wb + (lane & 15)) * TT;

    float c[25];
#pragma unroll
    for (int i = 0; i < 25; i++) c[i] = 0.0f;
    float facc = 0.0f;

    const half* aBase = As + (wb + g) * SA + tg * 2;
    const half* bBase = Bs + g * SB + tg * 2;

    for (int t = 0; t < TT; t++) {
        // prefetch next x (lanes 0..15 own rows wb..wb+15)
        float xn = 0.0f;
        if (lane < 16) {
            int tn = t + 1; if (tn >= TT) tn = TT - 1;
            xn = __ldg(xlane + tn);
        }

        // A fragments for all 4 k-chunks (h_{t-1}, x_t, 1, pad)
        uint32_t a[4][4];
#pragma unroll
        for (int kc = 0; kc < 4; kc++) {
            const half* p = aBase + kc * 16;
            a[kc][0] = lds32(p);
            a[kc][1] = lds32(p + 8 * SA);
            a[kc][2] = lds32(p + 8);
            a[kc][3] = lds32(p + 8 * SA + 8);
        }

        const bool last = (t == TT - 1);

#pragma unroll
        for (int nt = 0; nt < 25; nt++) {
            float d0 = 0.f, d1 = 0.f, d2 = 0.f, d3 = 0.f;
            const half* bp = bBase + nt * 8 * SB;
#pragma unroll
            for (int kc = 0; kc < 4; kc++) {
                uint32_t b0 = lds32(bp + kc * 16);
                uint32_t b1 = lds32(bp + kc * 16 + 8);
                mma16816(d0, d1, d2, d3,
                         a[kc][0], a[kc][1], a[kc][2], a[kc][3], b0, b1);
            }
            // n-tile covers hidden units 2nt (lanes tg0/1) and 2nt+1 (tg2/3):
            // cols (2tg,2tg+1) = (i,f) for even tg, (g,o) for odd tg.
            // Exchange across lane^1 so each lane owns one (row, j) result.
            float v0 = ev ? d2 : d0;
            float v1 = ev ? d3 : d1;
            float r0 = __shfl_xor_sync(0xffffffffu, v0, 1);
            float r1 = __shfl_xor_sync(0xffffffffu, v1, 1);
            float gi = ev ? d0 : r0;
            float gf = ev ? d1 : r1;
            float gg = ev ? r0 : d2;
            float go = ev ? r1 : d3;

            float I = sigf(gi);
            float F = sigf(gf);
            float G = tanhf_s(gg);
            float O = sigf(go);
            float cn = fmaf(F, c[nt], I * G);
            c[nt] = cn;
            float h = O * tanhf_s(cn);

            hdst[2 * nt + jofs] = __float2half_rn(h);
            if (last) facc = fmaf(h, FC[2 * nt + jofs], facc);
        }

        if (lane < 16)
            As[(wb + lane) * SA + 50] = __float2half_rn(xn);
        __syncwarp();
    }

    // fc head: lane tg0 (even j) + tg2 (odd j) cover row g; tg1+tg3 row g+8
    float r = facc + __shfl_xor_sync(0xffffffffu, facc, 2);
    if (tg < 2)
        out[ctabase + wb + rowloc] = r + __ldg(b_fc);
}

extern "C" void kernel_launch(void* const* d_in, const int* in_sizes, int n_in,
                              void* d_out, int out_size) {
    const float* x    = (const float*)d_in[0];
    const float* w_ih = (const float*)d_in[1];
    const float* w_hh = (const float*)d_in[2];
    const float* b_ih = (const float*)d_in[3];
    const float* b_hh = (const float*)d_in[4];
    const float* w_fc = (const float*)d_in[5];
    const float* b_fc = (const float*)d_in[6];

    lstm_mma_kernel<<<NCTA, TPB>>>(x, w_ih, w_hh, b_ih, b_hh,
                                   w_fc, b_fc, (float*)d_out);
}

// round 5
// speedup vs baseline: 6.9752x; 2.3461x over previous
#include <cuda_runtime.h>
#include <cuda_fp16.h>
#include <cstdint>

// LSTM_36318243455658 — HMMA batched LSTM, warp-pair N-split + double-buffered
// A tile + tanh.approx activations.
// CTA = 128 batch rows, 512 threads = 16 warps = 8 pairs; pair p owns rows
// 16p..16p+15. Within a pair: warp r=0 computes hidden j 0..25 (nt 0..12),
// warp r=1 computes j 26..49 (nt 13..24) and prefetches x. One named barrier
// per step per pair; A tile double-buffered so one barrier suffices.
// B = [w_hh | w_ih | b_ih+b_hh | 0pad], gate-interleaved n = 4j+gate, with
// 0.5x scale folded into i/f/o rows (sigmoid via tanh identity).

#define TT    2048
#define NB    16384
#define ROWS  128
#define NCTA  (NB / ROWS)
#define TPB   512
#define SA    56            // halves per A row (112B stride, bank = 28g+tg: clean)
#define SB    56
#define ABUF  (ROWS * SA)   // 7168 halves per A buffer
#define BSZ   (200 * SB)    // 11200 halves
// dyn smem: A0 | A1 | B | FC[52] f32 | part[256] f32
#define SMEM_BYTES (2*ABUF*2 + BSZ*2 + 52*4 + 256*4)

__device__ __forceinline__ uint32_t lds32(const half* p) {
    return *reinterpret_cast<const uint32_t*>(p);
}

__device__ __forceinline__ void mma16816(float& d0, float& d1, float& d2, float& d3,
                                         uint32_t a0, uint32_t a1, uint32_t a2, uint32_t a3,
                                         uint32_t b0, uint32_t b1) {
    asm volatile(
        "mma.sync.aligned.m16n8k16.row.col.f32.f16.f16.f32 "
        "{%0,%1,%2,%3}, {%4,%5,%6,%7}, {%8,%9}, {%0,%1,%2,%3};"
        : "+f"(d0), "+f"(d1), "+f"(d2), "+f"(d3)
        : "r"(a0), "r"(a1), "r"(a2), "r"(a3), "r"(b0), "r"(b1));
}
__device__ __forceinline__ void mma16808(float& d0, float& d1, float& d2, float& d3,
                                         uint32_t a0, uint32_t a1, uint32_t b0) {
    asm volatile(
        "mma.sync.aligned.m16n8k8.row.col.f32.f16.f16.f32 "
        "{%0,%1,%2,%3}, {%4,%5}, {%6}, {%0,%1,%2,%3};"
        : "+f"(d0), "+f"(d1), "+f"(d2), "+f"(d3)
        : "r"(a0), "r"(a1), "r"(b0));
}

__device__ __forceinline__ float tapx(float x) {
    float y;
    asm("tanh.approx.f32 %0, %1;" : "=f"(y) : "f"(x));
    return y;
}

__global__ void __launch_bounds__(TPB, 1)
lstm_mma2_kernel(const float* __restrict__ x,
                 const float* __restrict__ w_ih,
                 const float* __restrict__ w_hh,
                 const float* __restrict__ b_ih,
                 const float* __restrict__ b_hh,
                 const float* __restrict__ w_fc,
                 const float* __restrict__ b_fc,
                 float* __restrict__ out)
{
    extern __shared__ __align__(16) char dsmem[];
    half*  A0    = (half*)dsmem;
    half*  A1    = A0 + ABUF;
    half*  Bs    = A1 + ABUF;
    float* FC    = (float*)(Bs + BSZ);
    float* sPart = FC + 52;

    const int tid  = threadIdx.x;
    const int wid  = tid >> 5;
    const int lane = tid & 31;
    const int g    = lane >> 2;
    const int tg   = lane & 3;
    const int pair = wid >> 1;
    const int r    = wid & 1;            // 0: nt 0..12, 1: nt 13..24 + x
    const int wb   = pair * 16;
    const int barid = 1 + pair;          // named barriers 1..8
    const long long ctabase = (long long)blockIdx.x * ROWS;

    // ---- staging ----
    for (int i = tid; i < ABUF; i += TPB) {          // zero both A buffers
        reinterpret_cast<uint32_t*>(A0)[i & (ABUF/2 - 1)] = 0u;  // dummy pattern avoided below
    }
    // (simple, correct zeroing)
    for (int i = tid; i < 2 * ABUF / 2; i += TPB)
        reinterpret_cast<uint32_t*>(A0)[i] = 0u;
    for (int i = tid; i < BSZ; i += TPB) {
        int n = i / SB, k = i - n * SB;
        int j = n >> 2, gt = n & 3;
        int orig = gt * 50 + j;                      // PyTorch rows: i,f,g,o
        float v = 0.0f;
        if (k < 50)       v = w_hh[orig * 50 + k];
        else if (k == 50) v = w_ih[orig];
        else if (k == 51) v = b_ih[orig] + b_hh[orig];
        if (gt != 2) v *= 0.5f;                      // fold sigmoid half-scale
        Bs[i] = __float2half_rn(v);
    }
    if (tid < 52) FC[tid] = (tid < 50) ? w_fc[tid] : 0.0f;
    __syncthreads();
    if (tid < ROWS) {
        float x0 = __ldg(x + (ctabase + tid) * TT);
        A0[tid * SA + 50] = __float2half_rn(x0);
        A0[tid * SA + 51] = __float2half_rn(1.0f);
        A1[tid * SA + 51] = __float2half_rn(1.0f);
    }
    __syncthreads();

    const int  rowloc = g + (tg & 1) * 8;
    const bool ev     = (tg & 1) == 0;
    const int  jofs   = (tg >> 1);
    const int  aOff   = (wb + g) * SA + tg * 2;
    const int  hOff   = (wb + rowloc) * SA;
    const half* bBase = Bs + g * SB + tg * 2;
    const float* xlane = x + (ctabase + wb + (lane & 15)) * TT;

    const int ntLo = r ? 13 : 0;
    const int ntN  = r ? 12 : 13;

    float c[13];
#pragma unroll
    for (int i = 0; i < 13; i++) c[i] = 0.0f;
    float facc = 0.0f;

#pragma unroll 1
    for (int t = 0; t < TT; t++) {
        const half* rb = (t & 1) ? A1 : A0;
        half*       wbm = (t & 1) ? A0 : A1;

        float xn = 0.0f;
        if (r && lane < 16) {
            int tn = t + 1; if (tn >= TT) tn = TT - 1;
            xn = __ldg(xlane + tn);
        }

        // A fragments (h_{t-1} k0..47, then k48..55 = h48,h49,x,1,pad)
        const half* p = rb + aOff;
        uint32_t a16[3][4];
#pragma unroll
        for (int kc = 0; kc < 3; kc++) {
            a16[kc][0] = lds32(p + kc * 16);
            a16[kc][1] = lds32(p + kc * 16 + 8 * SA);
            a16[kc][2] = lds32(p + kc * 16 + 8);
            a16[kc][3] = lds32(p + kc * 16 + 8 * SA + 8);
        }
        uint32_t a8a = lds32(p + 48), a8b = lds32(p + 48 + 8 * SA);

        const bool last = (t == TT - 1);

#pragma unroll
        for (int q = 0; q < 13; q++) {
            if (q >= ntN) break;                     // r=1 does 12 tiles
            const int nt = ntLo + q;
            float d0 = 0.f, d1 = 0.f, d2 = 0.f, d3 = 0.f;
            const half* bp = bBase + nt * 8 * SB;
#pragma unroll
            for (int kc = 0; kc < 3; kc++) {
                uint32_t b0 = lds32(bp + kc * 16);
                uint32_t b1 = lds32(bp + kc * 16 + 8);
                mma16816(d0, d1, d2, d3,
                         a16[kc][0], a16[kc][1], a16[kc][2], a16[kc][3], b0, b1);
            }
            mma16808(d0, d1, d2, d3, a8a, a8b, lds32(bp + 48));

            // exchange so each lane owns one (row, j) gate quad
            float v0 = ev ? d2 : d0;
            float v1 = ev ? d3 : d1;
            float r0 = __shfl_xor_sync(0xffffffffu, v0, 1);
            float r1 = __shfl_xor_sync(0xffffffffu, v1, 1);
            float gi = ev ? d0 : r0;     // pre-act * 0.5 (folded)
            float gf = ev ? d1 : r1;     // pre-act * 0.5
            float gg = ev ? r0 : d2;     // full pre-act
            float go = ev ? r1 : d3;     // pre-act * 0.5

            float I = fmaf(0.5f, tapx(gi), 0.5f);
            float F = fmaf(0.5f, tapx(gf), 0.5f);
            float G = tapx(gg);
            float O = fmaf(0.5f, tapx(go), 0.5f);
            float cn = fmaf(F, c[q], I * G);
            c[q] = cn;
            float h = O * tapx(cn);

            wbm[hOff + 2 * nt + jofs] = __float2half_rn(h);
            if (last) facc = fmaf(h, FC[2 * nt + jofs], facc);
        }

        if (r && lane < 16)
            wbm[(wb + lane) * SA + 50] = __float2half_rn(xn);

        asm volatile("bar.sync %0, %1;" :: "r"(barid), "n"(64) : "memory");
    }

    // fc head: combine even/odd j lanes, then the two pair warps via smem
    float s = facc + __shfl_xor_sync(0xffffffffu, facc, 2);
    if (tg < 2) sPart[r * ROWS + wb + rowloc] = s;
    __syncthreads();
    if (tid < ROWS)
        out[ctabase + tid] = sPart[tid] + sPart[ROWS + tid] + __ldg(b_fc);
}

extern "C" void kernel_launch(void* const* d_in, const int* in_sizes, int n_in,
                              void* d_out, int out_size) {
    const float* x    = (const float*)d_in[0];
    const float* w_ih = (const float*)d_in[1];
    const float* w_hh = (const float*)d_in[2];
    const float* b_ih = (const float*)d_in[3];
    const float* b_hh = (const float*)d_in[4];
    const float* w_fc = (const float*)d_in[5];
    const float* b_fc = (const float*)d_in[6];

    cudaFuncSetAttribute(lstm_mma2_kernel,
                         cudaFuncAttributeMaxDynamicSharedMemorySize,
                         SMEM_BYTES);
    lstm_mma2_kernel<<<NCTA, TPB, SMEM_BYTES>>>(x, w_ih, w_hh, b_ih, b_hh,
                                                w_fc, b_fc, (float*)d_out);
}

// round 12
// speedup vs baseline: 8.4250x; 1.2079x over previous
#include <cuda_runtime.h>
#include <cuda_fp16.h>
#include <cstdint>

// LSTM_36318243455658 — HMMA batched LSTM, shuffle-free gate tiling +
// f16x2 activations.
// CTA = 128 rows, 512 threads, 8 warp-pairs; pair p owns rows 16p..16p+15.
// N tiled as 26 n8-tiles (13 tile-pairs, N padded 200->208): tile 2m holds
// (i,f) interleaved for hidden 4m+0..3, tile 2m+1 holds (g,o). Lane(g,tg)'s
// MMA outputs are then the full gate quad of hidden 4m+tg for rows g and g+8
// (no shuffles). Activations via tanh.approx.f16x2 on (row g, row g+8) pairs;
// c kept fp32. A = [h(0..49) | pad50,51 | x_t | 1 | pad], double-buffered.
// 0.5x sigmoid scale folded into B rows of gates i,f,o.

#define TT    2048
#define NB    16384
#define ROWS  128
#define NCTA  (NB / ROWS)
#define TPB   512
#define SA    56            // halves per A row (112B stride, conflict-free)
#define SB    56
#define NPAD  208           // padded N (26 n8-tiles)
#define ABUF  (ROWS * SA)   // halves per A buffer (7168)
#define BSZ   (NPAD * SB)   // 11648 halves
#define SMEM_BYTES (2*ABUF*2 + BSZ*2 + 52*4 + 256*4)   // 53200 B

__device__ __forceinline__ uint32_t lds32(const half* p) {
    return *reinterpret_cast<const uint32_t*>(p);
}

__device__ __forceinline__ void mma16816(float& d0, float& d1, float& d2, float& d3,
                                         uint32_t a0, uint32_t a1, uint32_t a2, uint32_t a3,
                                         uint32_t b0, uint32_t b1) {
    asm volatile(
        "mma.sync.aligned.m16n8k16.row.col.f32.f16.f16.f32 "
        "{%0,%1,%2,%3}, {%4,%5,%6,%7}, {%8,%9}, {%0,%1,%2,%3};"
        : "+f"(d0), "+f"(d1), "+f"(d2), "+f"(d3)
        : "r"(a0), "r"(a1), "r"(a2), "r"(a3), "r"(b0), "r"(b1));
}
__device__ __forceinline__ void mma16808(float& d0, float& d1, float& d2, float& d3,
                                         uint32_t a0, uint32_t a1, uint32_t b0) {
    asm volatile(
        "mma.sync.aligned.m16n8k8.row.col.f32.f16.f16.f32 "
        "{%0,%1,%2,%3}, {%4,%5}, {%6}, {%0,%1,%2,%3};"
        : "+f"(d0), "+f"(d1), "+f"(d2), "+f"(d3)
        : "r"(a0), "r"(a1), "r"(b0));
}

__device__ __forceinline__ half2 tanh2(half2 v) {
    uint32_t u = *reinterpret_cast<uint32_t*>(&v), y;
    asm("tanh.approx.f16x2 %0, %1;" : "=r"(y) : "r"(u));
    return *reinterpret_cast<half2*>(&y);
}

// one tile-pair: gates -> activations -> c update -> h writeback
template<int NP>
__device__ __forceinline__ void do_pairs(
    int m0, const half* bBase, const uint32_t (&a16)[3][4],
    uint32_t a8a, uint32_t a8b, float* c,
    half* wn, int hOffG, int hOffG8, int tg,
    bool last, float& faccL, float& faccH, const float* FC)
{
    const half2 H05 = __floats2half2_rn(0.5f, 0.5f);
#pragma unroll
    for (int q = 0; q < NP; q++) {
        const int m = m0 + q;
        const half* bp0 = bBase + (2 * m) * 8 * SB;      // (i,f) tile
        const half* bp1 = bp0 + 8 * SB;                  // (g,o) tile
        float d0 = 0.f, d1 = 0.f, d2 = 0.f, d3 = 0.f;
        float e0 = 0.f, e1 = 0.f, e2 = 0.f, e3 = 0.f;
#pragma unroll
        for (int kc = 0; kc < 3; kc++) {
            uint32_t b0 = lds32(bp0 + kc * 16);
            uint32_t b1 = lds32(bp0 + kc * 16 + 8);
            mma16816(d0, d1, d2, d3,
                     a16[kc][0], a16[kc][1], a16[kc][2], a16[kc][3], b0, b1);
            uint32_t c0 = lds32(bp1 + kc * 16);
            uint32_t c1 = lds32(bp1 + kc * 16 + 8);
            mma16816(e0, e1, e2, e3,
                     a16[kc][0], a16[kc][1], a16[kc][2], a16[kc][3], c0, c1);
        }
        mma16808(d0, d1, d2, d3, a8a, a8b, lds32(bp0 + 48));
        mma16808(e0, e1, e2, e3, a8a, a8b, lds32(bp1 + 48));

        // pack (row g, row g+8) pairs; i/f/o pre-acts carry folded 0.5x
        half2 I2 = tanh2(__floats2half2_rn(d0, d2));
        half2 F2 = tanh2(__floats2half2_rn(d1, d3));
        half2 G2 = tanh2(__floats2half2_rn(e0, e2));
        half2 O2 = tanh2(__floats2half2_rn(e1, e3));
        I2 = __hfma2(I2, H05, H05);
        F2 = __hfma2(F2, H05, H05);
        O2 = __hfma2(O2, H05, H05);
        half2 IG = __hmul2(I2, G2);

        float cn0 = fmaf(__low2float(F2),  c[2 * q],     __low2float(IG));
        float cn1 = fmaf(__high2float(F2), c[2 * q + 1], __high2float(IG));
        c[2 * q]     = cn0;
        c[2 * q + 1] = cn1;
        half2 T2 = tanh2(__floats2half2_rn(cn0, cn1));
        half2 H2 = __hmul2(O2, T2);

        const int j = 4 * m + tg;
        wn[hOffG  + j] = __low2half(H2);
        wn[hOffG8 + j] = __high2half(H2);
        if (last) {
            float w = FC[j];
            faccL = fmaf(__low2float(H2),  w, faccL);
            faccH = fmaf(__high2float(H2), w, faccH);
        }
    }
}

__global__ void __launch_bounds__(TPB, 1)
lstm_mma3_kernel(const float* __restrict__ x,
                 const float* __restrict__ w_ih,
                 const float* __restrict__ w_hh,
                 const float* __restrict__ b_ih,
                 const float* __restrict__ b_hh,
                 const float* __restrict__ w_fc,
                 const float* __restrict__ b_fc,
                 float* __restrict__ out)
{
    extern __shared__ __align__(16) char dsmem[];
    half*  A0    = (half*)dsmem;
    half*  A1    = A0 + ABUF;
    half*  Bs    = A1 + ABUF;
    float* FC    = (float*)(Bs + BSZ);
    float* sPart = FC + 52;

    const int tid  = threadIdx.x;
    const int wid  = tid >> 5;
    const int lane = tid & 31;
    const int g    = lane >> 2;
    const int tg   = lane & 3;
    const int pair = wid >> 1;
    const int r    = wid & 1;           // 0: pairs 0..6, 1: pairs 7..12 + x
    const int wb   = pair * 16;
    const int barid = 1 + pair;
    const long long ctabase = (long long)blockIdx.x * ROWS;

    // ---- staging ----
    for (int i = tid; i < ABUF; i += TPB)            // zero both A buffers
        reinterpret_cast<uint32_t*>(A0)[i] = 0u;     // ABUF u32 == 2*ABUF halves
    // B: n-tile 2m = (i,f) of hidden 4m+0..3 interleaved; 2m+1 = (g,o).
    // k<50: w_hh; k=52: w_ih; k=53: b_ih+b_hh; else 0. i/f/o rows scaled 0.5x.
    for (int i = tid; i < BSZ; i += TPB) {
        int n = i / SB, k = i - n * SB;
        int nt = n >> 3, par = nt & 1, mI = nt >> 1, cc = n & 7;
        int u = cc >> 1, bsel = cc & 1;
        int j = 4 * mI + u;
        int gt = par ? (bsel ? 3 : 2) : (bsel ? 1 : 0);   // i,f | g,o
        float v = 0.0f;
        if (j < 50) {
            int orig = gt * 50 + j;
            if (k < 50)       v = w_hh[orig * 50 + k];
            else if (k == 52) v = w_ih[orig];
            else if (k == 53) v = b_ih[orig] + b_hh[orig];
            if (gt != 2) v *= 0.5f;
        }
        Bs[i] = __float2half_rn(v);
    }
    if (tid < 52) FC[tid] = (tid < 50) ? w_fc[tid] : 0.0f;
    __syncthreads();
    if (tid < ROWS) {
        float x0 = __ldg(x + (ctabase + tid) * TT);
        A0[tid * SA + 52] = __float2half_rn(x0);
        A0[tid * SA + 53] = __float2half_rn(1.0f);
        A1[tid * SA + 53] = __float2half_rn(1.0f);
    }
    __syncthreads();

    const int  aOff   = (wb + g) * SA + tg * 2;
    const int  hOffG  = (wb + g) * SA;
    const int  hOffG8 = (wb + g + 8) * SA;
    const half* bBase = Bs + g * SB + tg * 2;
    const float* xlane = x + (ctabase + wb + (lane & 15)) * TT;

    float c[14];
#pragma unroll
    for (int i = 0; i < 14; i++) c[i] = 0.0f;
    float faccL = 0.0f, faccH = 0.0f;

#pragma unroll 1
    for (int t = 0; t < TT; t++) {
        const half* rb = (t & 1) ? A1 : A0;
        half*       wn = (t & 1) ? A0 : A1;

        float xn = 0.0f;
        if (r && lane < 16) {
            int tn = t + 1; if (tn >= TT) tn = TT - 1;
            xn = __ldg(xlane + tn);
        }

        // A fragments: k0..47 (3 x k16) + k48..55 (k8: h48,h49,p,p,x,1,p,p)
        const half* p = rb + aOff;
        uint32_t a16[3][4];
#pragma unroll
        for (int kc = 0; kc < 3; kc++) {
            a16[kc][0] = lds32(p + kc * 16);
            a16[kc][1] = lds32(p + kc * 16 + 8 * SA);
            a16[kc][2] = lds32(p + kc * 16 + 8);
            a16[kc][3] = lds32(p + kc * 16 + 8 * SA + 8);
        }
        uint32_t a8a = lds32(p + 48), a8b = lds32(p + 48 + 8 * SA);

        const bool last = (t == TT - 1);

        if (r == 0)
            do_pairs<7>(0, bBase, a16, a8a, a8b, c, wn, hOffG, hOffG8, tg,
                        last, faccL, faccH, FC);
        else
            do_pairs<6>(7, bBase, a16, a8a, a8b, c, wn, hOffG, hOffG8, tg,
                        last, faccL, faccH, FC);

        if (r && lane < 16)
            wn[(wb + lane) * SA + 52] = __float2half_rn(xn);

        asm volatile("bar.sync %0, %1;" :: "r"(barid), "n"(64) : "memory");
    }

    // fc head: reduce over tg lanes (hidden split), then over r warps
    faccL += __shfl_xor_sync(0xffffffffu, faccL, 1);
    faccL += __shfl_xor_sync(0xffffffffu, faccL, 2);
    faccH += __shfl_xor_sync(0xffffffffu, faccH, 1);
    faccH += __shfl_xor_sync(0xffffffffu, faccH, 2);
    if (tg == 0) {
        sPart[r * ROWS + wb + g]     = faccL;
        sPart[r * ROWS + wb + g + 8] = faccH;
    }
    __syncthreads();
    if (tid < ROWS)
        out[ctabase + tid] = sPart[tid] + sPart[ROWS + tid] + __ldg(b_fc);
}

extern "C" void kernel_launch(void* const* d_in, const int* in_sizes, int n_in,
                              void* d_out, int out_size) {
    const float* x    = (const float*)d_in[0];
    const float* w_ih = (const float*)d_in[1];
    const float* w_hh = (const float*)d_in[2];
    const float* b_ih = (const float*)d_in[3];
    const float* b_hh = (const float*)d_in[4];
    const float* w_fc = (const float*)d_in[5];
    const float* b_fc = (const float*)d_in[6];

    cudaFuncSetAttribute(lstm_mma3_kernel,
                         cudaFuncAttributeMaxDynamicSharedMemorySize,
                         SMEM_BYTES);
    lstm_mma3_kernel<<<NCTA, TPB, SMEM_BYTES>>>(x, w_ih, w_hh, b_ih, b_hh,
                                                w_fc, b_fc, (float*)d_out);
}